// round 1
// baseline (speedup 1.0000x reference)
#include <cuda_runtime.h>
#include <cuda_bf16.h>
#include <cstdint>

// Problem constants
#define BATCH   32
#define NN      64
#define DD      512
#define MM      2080          // N*(N+1)/2
#define SORTN   4096
#define TOPK    5
#define NEIGH   16
#define NEGK    16
#define TOTALS  85            // TOPK*(NEIGH+1)
#define KK      101           // NEGK + TOTALS
#define NSEG    65            // 2080/32

// Output layout (concatenated float32): feat, pred_s_e, offset, score
#define FEAT_BASE 0
#define SE_BASE   (BATCH*KK*DD)                 // 1654784
#define OFF_BASE  (SE_BASE + BATCH*KK*2)        // 1661248
#define SC_BASE   (OFF_BASE + BATCH*KK*2)       // 1667712

__device__ unsigned int g_rc[BATCH * KK];       // r*64+c per selected proposal

__device__ __forceinline__ unsigned int float_desc_key(float s) {
    unsigned int u = __float_as_uint(s);
    unsigned int k = (u & 0x80000000u) ? ~u : (u | 0x80000000u); // ascending map
    return ~k;                                                   // descending
}

__global__ void __launch_bounds__(1024, 1)
select_kernel(const float* __restrict__ score_pred,
              const float* __restrict__ offset_gt,
              const float* __restrict__ tmap,
              float* __restrict__ out)
{
    __shared__ unsigned long long keys[SORTN];          // 32768 B
    __shared__ unsigned short rc[MM];                   // r | c<<8 (original order)
    __shared__ unsigned short smom[MM];                 // s | e<<8 (sorted order)
    __shared__ unsigned int maskw[NSEG], supw[NSEG], selw[NSEG];
    __shared__ unsigned short unsup_idx[MM];
    __shared__ unsigned short sel_idx[TOTALS];
    __shared__ unsigned int upref[NSEG + 1], spref[NSEG + 1];
    __shared__ int sh_i, sh_cnt;

    const int b   = blockIdx.x;
    const int tid = threadIdx.x;

    // ---------------- Phase A: load scores, build sort keys ----------------
    for (int e = tid; e < SORTN; e += 1024) {
        unsigned long long key;
        if (e < MM) {
            // invert linear triu index -> (r, c)
            int r = (int)floorf((129.0f - sqrtf(16641.0f - 8.0f * (float)e)) * 0.5f);
            if (r < 0) r = 0; if (r > 63) r = 63;
            while (r > 0  && (r * (129 - r)) / 2 > e) --r;
            while (r < 63 && ((r + 1) * (128 - r)) / 2 <= e) ++r;
            int c = r + (e - (r * (129 - r)) / 2);
            rc[e] = (unsigned short)(r | (c << 8));
            float s = score_pred[b * (NN * NN) + r * NN + c];
            key = ((unsigned long long)float_desc_key(s) << 32) | (unsigned int)e;
        } else {
            key = ~0ULL;
        }
        keys[e] = key;
    }
    __syncthreads();

    // ---------------- Phase B: bitonic sort (ascending) ----------------
    for (int k = 2; k <= SORTN; k <<= 1) {
        for (int j = k >> 1; j > 0; j >>= 1) {
            #pragma unroll
            for (int ii = 0; ii < SORTN / 1024; ++ii) {
                int i = tid + ii * 1024;
                int ixj = i ^ j;
                if (ixj > i) {
                    bool up = ((i & k) == 0);
                    unsigned long long a = keys[i];
                    unsigned long long bb = keys[ixj];
                    if ((a > bb) == up) { keys[i] = bb; keys[ixj] = a; }
                }
            }
            __syncthreads();
        }
    }

    // ---------------- Phase C: sorted moments, init state ----------------
    for (int i = tid; i < MM; i += 1024) {
        unsigned int e = (unsigned int)keys[i];
        unsigned int rcv = rc[e];
        int s = rcv & 0xFF;
        int en = (rcv >> 8) + 1;
        smom[i] = (unsigned short)(s | (en << 8));
    }
    if (tid < NSEG) { supw[tid] = 0u; selw[tid] = 0u; }
    if (tid == 0)   { sh_i = 0; sh_cnt = 0; }

    // ---------------- Phase D: greedy NMS ----------------
    for (;;) {
        __syncthreads();
        int i = sh_i, cnt = sh_cnt;
        if (cnt >= TOPK || i >= MM - 1) break;

        bool freei = (((supw[i >> 5] >> (i & 31)) & 1u) == 0u);
        if (!freei) {
            __syncthreads();
            if (tid == 0) sh_i = i + 1;
            continue;
        }

        unsigned int mi = smom[i];
        int si = mi & 0xFF, ei = mi >> 8;

        #pragma unroll
        for (int rd = 0; rd < 3; ++rd) {
            int e2 = tid + rd * 1024;
            bool mk = false;
            if (e2 < MM && e2 > i) {
                unsigned int mm = smom[e2];
                int s3 = mm & 0xFF, e3 = mm >> 8;
                int inter = min(e3, ei) - max(s3, si);
                if (inter > 0) {
                    int uni = max(e3, ei) - min(s3, si);
                    mk = (2 * inter > uni);           // == (iou > 0.5) exactly
                }
            }
            unsigned int bal = __ballot_sync(0xFFFFFFFFu, mk);
            int seg = (tid >> 5) + rd * 32;
            if ((tid & 31) == 0 && seg < NSEG) maskw[seg] = bal;
        }
        __syncthreads();

        if (tid < NSEG) {
            unsigned int w = maskw[tid];
            if (w) atomicOr(&supw[tid], w);
        }
        if (tid == 0) {
            // first NEIGH masked elements -> sel
            int rem = NEIGH;
            for (int s2 = 0; s2 < NSEG && rem > 0; ++s2) {
                unsigned int w = maskw[s2];
                if (!w) continue;
                int pc = __popc(w);
                if (pc <= rem) { atomicOr(&selw[s2], w); rem -= pc; }
                else {
                    unsigned int x = 0;
                    for (int q = 0; q < rem; ++q) {
                        unsigned int lsb = w & (0u - w);
                        x |= lsb; w ^= lsb;
                    }
                    atomicOr(&selw[s2], x);
                    rem = 0;
                }
            }
            atomicOr(&supw[i >> 5], 1u << (i & 31));
            atomicOr(&selw[i >> 5], 1u << (i & 31));
            sh_i = i + 1;
            sh_cnt = cnt + 1;
        }
    }
    // loop-exit barrier already executed (uniform break right after __syncthreads)

    // ---------------- Phase E: compactions ----------------
    if (tid == 0) {
        unsigned int runU = 0, runS = 0;
        #pragma unroll
        for (int s2 = 0; s2 < NSEG; ++s2) {
            upref[s2] = runU; runU += __popc(~supw[s2]);
            spref[s2] = runS; runS += __popc(selw[s2]);
        }
        upref[NSEG] = runU;           // n_unsup
        spref[NSEG] = runS;           // n_sel
    }
    for (int t = tid; t < MM; t += 1024) unsup_idx[t] = (unsigned short)(MM - 1);
    if (tid < TOTALS) sel_idx[tid] = (unsigned short)(MM - 1);
    __syncthreads();

    for (int e2 = tid; e2 < MM; e2 += 1024) {
        int s2 = e2 >> 5;
        unsigned int bit = 1u << (e2 & 31);
        unsigned int low = bit - 1u;
        unsigned int uw = ~supw[s2];
        if (uw & bit) unsup_idx[upref[s2] + __popc(uw & low)] = (unsigned short)e2;
        unsigned int sw = selw[s2];
        if (sw & bit) sel_idx[spref[s2] + __popc(sw & low)] = (unsigned short)e2;
    }
    __syncthreads();

    // ---------------- Phase F: final index assembly + small outputs ----------------
    if (tid < KK) {
        int n_unsup = (int)upref[NSEG];
        int n_sel   = (int)spref[NSEG];
        int pad     = TOTALS - n_sel;

        int idxS;
        if (tid < NEGK) {
            int t = n_unsup - 1 - tid;
            if (t < 0) t = 0;
            if (t > MM - 1) t = MM - 1;
            idxS = unsup_idx[t];
        } else {
            int p = tid - NEGK;
            if (p < pad) idxS = unsup_idx[p];
            else {
                int q = p - pad;
                if (q > TOTALS - 1) q = TOTALS - 1;
                idxS = sel_idx[q];
            }
        }
        unsigned int orig = (unsigned int)keys[idxS];   // order[idx_sorted]
        unsigned int rcv  = rc[orig];
        int r = rcv & 0xFF;
        int c = rcv >> 8;

        int gk = b * KK + tid;
        g_rc[gk] = (unsigned int)(r * NN + c);

        out[SE_BASE + gk * 2 + 0] = (float)r;
        out[SE_BASE + gk * 2 + 1] = (float)(c + 1);

        size_t oidx = ((size_t)(b * NN + r) * NN + c) * 2;
        out[OFF_BASE + gk * 2 + 0] = offset_gt[oidx + 0];
        out[OFF_BASE + gk * 2 + 1] = offset_gt[oidx + 1];

        out[SC_BASE + gk] = tmap[(size_t)(b * NN + r) * NN + c];
    }
}

__global__ void __launch_bounds__(128, 8)
gather_kernel(const float* __restrict__ map2d, float* __restrict__ out)
{
    int row = blockIdx.x;                 // 0 .. B*K-1
    int b   = row / KK;
    unsigned int rcv = g_rc[row];
    const float4* src = (const float4*)(map2d + ((size_t)(b * (NN * NN)) + rcv) * DD);
    float4* dst = (float4*)(out + FEAT_BASE + (size_t)row * DD);
    dst[threadIdx.x] = src[threadIdx.x];  // 128 threads * float4 = 512 floats
}

extern "C" void kernel_launch(void* const* d_in, const int* in_sizes, int n_in,
                              void* d_out, int out_size)
{
    const float* score_pred = (const float*)d_in[0];
    // d_in[1] = map2d_mask (deterministic triu — not needed)
    const float* map2d      = (const float*)d_in[2];
    const float* offset_gt  = (const float*)d_in[3];
    const float* tmap       = (const float*)d_in[4];
    float* out = (float*)d_out;

    select_kernel<<<BATCH, 1024>>>(score_pred, offset_gt, tmap, out);
    gather_kernel<<<BATCH * KK, 128>>>(map2d, out);
}

// round 2
// speedup vs baseline: 2.1346x; 2.1346x over previous
#include <cuda_runtime.h>
#include <cuda_bf16.h>
#include <cstdint>

// Problem constants
#define BATCH   32
#define NN      64
#define DD      512
#define MM      2080          // N*(N+1)/2
#define SORTN   4096
#define TOPK    5
#define NEIGH   16
#define NEGK    16
#define TOTALS  85            // TOPK*(NEIGH+1)
#define KK      101           // NEGK + TOTALS
#define NSEG    65            // ceil(2080/32)

// Output layout (concatenated float32): feat, pred_s_e, offset, score
#define FEAT_BASE 0
#define SE_BASE   (BATCH*KK*DD)
#define OFF_BASE  (SE_BASE + BATCH*KK*2)
#define SC_BASE   (OFF_BASE + BATCH*KK*2)

__device__ unsigned int g_rc[BATCH * KK];       // r*64+c per selected proposal

typedef unsigned long long u64;

__device__ __forceinline__ unsigned int float_desc_key(float s) {
    unsigned int u = __float_as_uint(s);
    unsigned int k = (u & 0x80000000u) ? ~u : (u | 0x80000000u); // ascending map
    return ~k;                                                   // descending
}

__device__ __forceinline__ u64 u64min(u64 a, u64 b) { return a < b ? a : b; }
__device__ __forceinline__ u64 u64max(u64 a, u64 b) { return a > b ? a : b; }

__device__ __forceinline__ void cswap(u64 &a, u64 &b, bool up) {
    if ((a > b) == up) { u64 t = a; a = b; b = t; }
}

// Register/warp-local bitonic stages for j = jstart down to 1 (jstart <= 64).
// Element of K[q] has global index ebase + q*32 (ebase = warp*128 + lane).
__device__ __forceinline__ void reg_phase(u64 K[4], int k, int jstart, int ebase) {
    int j = jstart;
    if (j >= 64) {                                  // j=64: (K0,K2),(K1,K3)
        #pragma unroll
        for (int q = 0; q < 2; ++q) {
            bool up = (((ebase + q * 32) & k) == 0);
            cswap(K[q], K[q + 2], up);
        }
        j = 32;
    }
    if (j >= 32) {                                  // j=32: (K0,K1),(K2,K3)
        #pragma unroll
        for (int q = 0; q < 4; q += 2) {
            bool up = (((ebase + q * 32) & k) == 0);
            cswap(K[q], K[q + 1], up);
        }
        j = 16;
    }
    for (; j >= 1; j >>= 1) {                       // shuffle stages
        #pragma unroll
        for (int q = 0; q < 4; ++q) {
            int e = ebase + q * 32;
            bool up = ((e & k) == 0);
            u64 o = __shfl_xor_sync(0xFFFFFFFFu, K[q], j);
            bool upper = (e & j) != 0;              // == lane&j (j<=16)
            K[q] = (up != upper) ? u64min(K[q], o) : u64max(K[q], o);
        }
    }
}

__global__ void __launch_bounds__(1024, 1)
select_kernel(const float* __restrict__ score_pred,
              const float* __restrict__ offset_gt,
              const float* __restrict__ tmap,
              float* __restrict__ out)
{
    __shared__ u64 skeys[SORTN];                    // 32768 B
    __shared__ unsigned short rc[MM];               // r | c<<8 (original order)
    __shared__ unsigned short smom[MM];             // s | e<<8 (sorted order)
    __shared__ unsigned int maskw[NSEG], supw[NSEG], selw[NSEG];
    __shared__ unsigned short unsup_idx[MM];
    __shared__ unsigned short sel_idx[TOTALS];
    __shared__ unsigned int upref[NSEG + 1], spref[NSEG + 1];

    const int b    = blockIdx.x;
    const int tid  = threadIdx.x;
    const int lane = tid & 31;
    const int warp = tid >> 5;
    const int ebase = warp * 128 + lane;

    // ---------------- Phase A: build keys (scatter by (r,c)) ----------------
    for (int idx = tid; idx < SORTN; idx += 1024) skeys[idx] = ~0ULL;
    __syncthreads();
    for (int idx = tid; idx < NN * NN; idx += 1024) {
        int r = idx >> 6, c = idx & 63;
        if (c >= r) {
            int e = (r * (129 - r)) / 2 + (c - r);
            float s = score_pred[b * (NN * NN) + idx];
            skeys[e] = ((u64)float_desc_key(s) << 32) | (unsigned int)e;
            rc[e] = (unsigned short)(r | (c << 8));
        }
    }
    __syncthreads();

    // ---------------- Phase B: register-blocked bitonic sort ----------------
    u64 K[4];
    #pragma unroll
    for (int q = 0; q < 4; ++q) K[q] = skeys[warp * 128 + q * 32 + lane];

    // k = 2..128: fully warp-local, zero barriers
    for (int k = 2; k <= 128; k <<= 1) reg_phase(K, k, k >> 1, ebase);

    // k = 256..4096: smem stages for j>=128, then warp-local tail
    for (int k = 256; k <= SORTN; k <<= 1) {
        #pragma unroll
        for (int q = 0; q < 4; ++q) skeys[warp * 128 + q * 32 + lane] = K[q];
        __syncthreads();
        for (int j = k >> 1; j >= 128; j >>= 1) {
            #pragma unroll
            for (int t2i = 0; t2i < 2; ++t2i) {
                int t2 = tid + t2i * 1024;
                int i = ((t2 & ~(j - 1)) << 1) | (t2 & (j - 1));
                int p = i | j;
                bool up = ((i & k) == 0);
                u64 a = skeys[i], bb = skeys[p];
                if ((a > bb) == up) { skeys[i] = bb; skeys[p] = a; }
            }
            __syncthreads();
        }
        #pragma unroll
        for (int q = 0; q < 4; ++q) K[q] = skeys[warp * 128 + q * 32 + lane];
        reg_phase(K, k, 64, ebase);
    }
    #pragma unroll
    for (int q = 0; q < 4; ++q) skeys[warp * 128 + q * 32 + lane] = K[q];
    __syncthreads();

    // ---------------- Phase C: sorted moments, init state ----------------
    for (int i = tid; i < MM; i += 1024) {
        unsigned int e = (unsigned int)skeys[i];
        unsigned int rcv = rc[e];
        int s = rcv & 0xFF;
        int en = (rcv >> 8) + 1;
        smom[i] = (unsigned short)(s | (en << 8));
    }
    if (tid < NSEG) { supw[tid] = 0u; selw[tid] = 0u; }
    __syncthreads();

    // ---------------- Phase D: greedy NMS (replicated control) ----------------
    {
        int i = 0, cnt = 0;
        while (cnt < TOPK) {
            // All threads scan for next free i (broadcast smem reads, identical
            // control flow across the block -> barriers below stay uniform).
            while (i < MM - 1 && ((supw[i >> 5] >> (i & 31)) & 1u)) ++i;
            if (i >= MM - 1) break;

            unsigned int mi = smom[i];
            int si = mi & 0xFF, ei = mi >> 8;

            #pragma unroll
            for (int rd = 0; rd < 3; ++rd) {
                int e2 = tid + rd * 1024;
                bool mk = false;
                if (e2 < MM) {
                    if (e2 == i) mk = true;
                    else if (e2 > i) {
                        unsigned int mmv = smom[e2];
                        int s3 = mmv & 0xFF, e3 = mmv >> 8;
                        int inter = min(e3, ei) - max(s3, si);
                        if (inter > 0) {
                            int uni = max(e3, ei) - min(s3, si);
                            mk = (2 * inter > uni);      // == (iou > 0.5) exactly
                        }
                    }
                }
                unsigned int bal = __ballot_sync(0xFFFFFFFFu, mk);
                int seg = (tid >> 5) + rd * 32;
                if (lane == 0 && seg < NSEG) maskw[seg] = bal;
            }
            __syncthreads();

            if (tid < NSEG) supw[tid] |= maskw[tid];     // single writer per word
            if (tid == 0) {
                // first NEIGH masked (e>i) elements -> sel, plus bit i
                int rem = NEIGH;
                int iseg = i >> 5;
                unsigned int ibit = 1u << (i & 31);
                for (int s2 = iseg; s2 < NSEG && rem > 0; ++s2) {
                    unsigned int w = maskw[s2];
                    if (s2 == iseg) w &= ~ibit;          // exclude e==i
                    if (!w) continue;
                    int pc = __popc(w);
                    if (pc <= rem) { selw[s2] |= w; rem -= pc; }
                    else {
                        unsigned int x = 0;
                        for (int q2 = 0; q2 < rem; ++q2) {
                            unsigned int lsb = w & (0u - w);
                            x |= lsb; w ^= lsb;
                        }
                        selw[s2] |= x;
                        rem = 0;
                    }
                }
                selw[iseg] |= ibit;
            }
            __syncthreads();
            ++i; ++cnt;
        }
        __syncthreads();   // uniform: all threads exit the loop identically
    }

    // ---------------- Phase E: compactions ----------------
    if (tid == 0) {
        unsigned int runU = 0, runS = 0;
        #pragma unroll
        for (int s2 = 0; s2 < NSEG; ++s2) {
            upref[s2] = runU; runU += __popc(~supw[s2]);
            spref[s2] = runS; runS += __popc(selw[s2]);
        }
        upref[NSEG] = runU;           // n_unsup (incl. tail-pad bits? no: NSEG*32=2080 exact)
        spref[NSEG] = runS;           // n_sel
    }
    for (int t = tid; t < MM; t += 1024) unsup_idx[t] = (unsigned short)(MM - 1);
    if (tid < TOTALS) sel_idx[tid] = (unsigned short)(MM - 1);
    __syncthreads();

    for (int e2 = tid; e2 < MM; e2 += 1024) {
        int s2 = e2 >> 5;
        unsigned int bit = 1u << (e2 & 31);
        unsigned int low = bit - 1u;
        unsigned int uw = ~supw[s2];
        if (uw & bit) unsup_idx[upref[s2] + __popc(uw & low)] = (unsigned short)e2;
        unsigned int sw = selw[s2];
        if (sw & bit) sel_idx[spref[s2] + __popc(sw & low)] = (unsigned short)e2;
    }
    __syncthreads();

    // ---------------- Phase F: final index assembly + small outputs ----------------
    if (tid < KK) {
        int n_unsup = (int)upref[NSEG];
        int n_sel   = (int)spref[NSEG];
        int pad     = TOTALS - n_sel;

        int idxS;
        if (tid < NEGK) {
            int t = n_unsup - 1 - tid;
            if (t < 0) t = 0;
            if (t > MM - 1) t = MM - 1;
            idxS = unsup_idx[t];
        } else {
            int p = tid - NEGK;
            if (p < pad) idxS = unsup_idx[p];
            else {
                int q = p - pad;
                if (q > TOTALS - 1) q = TOTALS - 1;
                idxS = sel_idx[q];
            }
        }
        unsigned int orig = (unsigned int)skeys[idxS];   // order[idx_sorted]
        unsigned int rcv  = rc[orig];
        int r = rcv & 0xFF;
        int c = rcv >> 8;

        int gk = b * KK + tid;
        g_rc[gk] = (unsigned int)(r * NN + c);

        out[SE_BASE + gk * 2 + 0] = (float)r;
        out[SE_BASE + gk * 2 + 1] = (float)(c + 1);

        size_t oidx = ((size_t)(b * NN + r) * NN + c) * 2;
        out[OFF_BASE + gk * 2 + 0] = offset_gt[oidx + 0];
        out[OFF_BASE + gk * 2 + 1] = offset_gt[oidx + 1];

        out[SC_BASE + gk] = tmap[(size_t)(b * NN + r) * NN + c];
    }
}

__global__ void __launch_bounds__(256, 4)
gather_kernel(const float* __restrict__ map2d, float* __restrict__ out)
{
    int row = blockIdx.x * 8 + (threadIdx.x >> 5);   // 8 rows per CTA
    if (row >= BATCH * KK) return;
    int lane = threadIdx.x & 31;
    int b = row / KK;
    const float4* __restrict__ src =
        (const float4*)(map2d + ((size_t)(b * (NN * NN)) + g_rc[row]) * DD);
    float4* __restrict__ dst = (float4*)(out + FEAT_BASE + (size_t)row * DD);
    // batch 4 independent 128-bit loads (MLP=4) before storing
    float4 v0 = src[lane];
    float4 v1 = src[lane + 32];
    float4 v2 = src[lane + 64];
    float4 v3 = src[lane + 96];
    dst[lane]      = v0;
    dst[lane + 32] = v1;
    dst[lane + 64] = v2;
    dst[lane + 96] = v3;
}

extern "C" void kernel_launch(void* const* d_in, const int* in_sizes, int n_in,
                              void* d_out, int out_size)
{
    const float* score_pred = (const float*)d_in[0];
    // d_in[1] = map2d_mask (deterministic triu — not needed)
    const float* map2d      = (const float*)d_in[2];
    const float* offset_gt  = (const float*)d_in[3];
    const float* tmap       = (const float*)d_in[4];
    float* out = (float*)d_out;

    select_kernel<<<BATCH, 1024>>>(score_pred, offset_gt, tmap, out);
    gather_kernel<<<(BATCH * KK + 7) / 8, 256>>>(map2d, out);
}